// round 12
// baseline (speedup 1.0000x reference)
#include <cuda_runtime.h>
#include <cuda_bf16.h>
#include <cstddef>
#include <cstdint>

// Problem constants
#define N_TOK   32768
#define DIM     128
#define KCODES  1024
#define NCB     8
#define M_TILE  128
#define TPB     256
#define GRID_MAIN (N_TOK / M_TILE)    // 256
#define NCHUNK  256                   // 32-code chunks across all codebooks

// Device scratch (no allocations allowed)
__device__ float g_wn[NCB * KCODES];
__device__ float g_wnmax[NCB];
__device__ float g_part[GRID_MAIN];
__device__ __align__(16) __nv_bfloat16 g_cb16[(size_t)NCB * KCODES * DIM];

// smem offsets (16B aligned)
#define SO_RES   0         // float [128][129]   66048 B
#define SO_B     66048     // bf16 2 x [32][136] 17408 B
#define SO_WN    83456     // float [1024]        4096 B
#define SO_CODES 87552     // int [8][128]        4096 B
#define SO_RED   91648     // float [256]         1024 B
#define SMEM_REQ 92672
#define BBUF     8704      // one B buffer: 32*136*2

extern __shared__ char smraw[];

// ---------------------------------------------------------------------------
__device__ __forceinline__ uint32_t smem_u32(const void* p) {
    uint32_t a;
    asm("{ .reg .u64 t; cvta.to.shared.u64 t, %1; cvt.u32.u64 %0, t; }"
        : "=r"(a) : "l"(p));
    return a;
}
__device__ __forceinline__ void cp_async16(uint32_t dst, const void* src) {
    asm volatile("cp.async.cg.shared.global [%0], [%1], 16;\n" :: "r"(dst), "l"(src));
}
#define CP_COMMIT() asm volatile("cp.async.commit_group;\n" ::: "memory")
#define CP_WAIT(n)  asm volatile("cp.async.wait_group %0;\n" :: "n"(n) : "memory")

// pack two f32 into bf16x2: result.low = lo (even dim), result.high = hi (odd dim)
__device__ __forceinline__ uint32_t bf2(float lo, float hi) {
    uint32_t r;
    asm("cvt.rn.satfinite.bf16x2.f32 %0, %1, %2;" : "=r"(r) : "f"(hi), "f"(lo));
    return r;
}
// explicit HMMA: D(16x8,f32) += A(16x16,bf16,row) * B(16x8,bf16,col)
__device__ __forceinline__ void mma16816(float* c, const uint32_t* a,
                                         uint32_t b0, uint32_t b1) {
    asm volatile(
        "mma.sync.aligned.m16n8k16.row.col.f32.bf16.bf16.f32 "
        "{%0,%1,%2,%3}, {%4,%5,%6,%7}, {%8,%9}, {%0,%1,%2,%3};"
        : "+f"(c[0]), "+f"(c[1]), "+f"(c[2]), "+f"(c[3])
        : "r"(a[0]), "r"(a[1]), "r"(a[2]), "r"(a[3]), "r"(b0), "r"(b1));
}

// ---------------------------------------------------------------------------
// Kernel 1: ||w||^2 per code (frozen chain)
// ---------------------------------------------------------------------------
__global__ void wnorm_kernel(const float* __restrict__ cb) {
    int gwarp = (blockIdx.x * blockDim.x + threadIdx.x) >> 5;
    int lane  = threadIdx.x & 31;
    if (gwarp >= NCB * KCODES) return;
    const float* w = cb + (size_t)gwarp * DIM;
    float s = 0.f;
    #pragma unroll
    for (int i = 0; i < DIM / 32; ++i) { float v = w[lane + 32 * i]; s = __fmaf_rn(v, v, s); }
    #pragma unroll
    for (int o = 16; o > 0; o >>= 1) s = __fadd_rn(s, __shfl_xor_sync(0xFFFFFFFFu, s, o));
    if (lane == 0) g_wn[gwarp] = s;
}

// Kernel 1b: per-codebook max ||w||^2
__global__ void wnmax_kernel() {
    __shared__ float red[256];
    int c = blockIdx.x, t = threadIdx.x;
    float mx = 0.f;
    for (int e = t; e < KCODES; e += 256) mx = fmaxf(mx, g_wn[c * KCODES + e]);
    red[t] = mx; __syncthreads();
    for (int s = 128; s > 0; s >>= 1) { if (t < s) red[t] = fmaxf(red[t], red[t + s]); __syncthreads(); }
    if (t == 0) g_wnmax[c] = red[0];
}

// Kernel 1c: codebook fp32 -> bf16 (row-major, same layout)
__global__ void cb16_kernel(const float* __restrict__ cb) {
    int i = blockIdx.x * blockDim.x + threadIdx.x;
    if (i < NCB * KCODES * DIM) g_cb16[i] = __float2bfloat16(cb[i]);
}

// ---------------------------------------------------------------------------
// stage one 32-code chunk: g_cb16 rows -> Bs[code][dim] bf16 (stride 136 elem)
// ---------------------------------------------------------------------------
__device__ __forceinline__ void stage_chunk(char* S, int g, int tid) {
    uint32_t dstb = smem_u32(S + SO_B + (g & 1) * BBUF);
    const char* src = (const char*)g_cb16 + (size_t)g * 32 * DIM * 2;   // 8192B
    #pragma unroll
    for (int r = 0; r < 2; ++r) {
        int e = tid + r * TPB;          // 0..511 x 16B
        int code = e >> 4, q = e & 15;
        cp_async16(dstb + code * 272 + q * 16, src + e * 16);
    }
    CP_COMMIT();
}

// ---------------------------------------------------------------------------
// Kernel 2: main. Block = 128 tokens, 8 warps; warp owns 16 tokens.
// Explicit mma.m16n8k16 prune (C in regs, top-2/lane/row, 8 cand/token via
// quad merge) + exact fp32 rescore with the FROZEN chain -> bit-exact codes.
// Warp-uniform ballot fallback (exact full scan) guarantees soundness.
// ---------------------------------------------------------------------------
__global__ __launch_bounds__(TPB, 2) void rvq_main(
    const float* __restrict__ emb, const float* __restrict__ cb,
    float* __restrict__ out_codes, float* __restrict__ out_quant)
{
    char* S = smraw;
    float* resf    = reinterpret_cast<float*>(S + SO_RES);
    float* wn_s    = reinterpret_cast<float*>(S + SO_WN);
    int*   codes_s = reinterpret_cast<int*>(S + SO_CODES);
    float* red     = reinterpret_cast<float*>(S + SO_RED);

    const int tid  = threadIdx.x;
    const int wid  = tid >> 5;
    const int lane = tid & 31;
    const int gid  = lane >> 2;        // group id 0..7 -> rows gid, gid+8
    const int cid  = lane & 3;         // thread-in-group -> k/n sub-columns
    const int n0   = blockIdx.x * M_TILE;
    const int row0 = wid * 16 + gid;   // token index within block
    const int row1 = row0 + 8;

    stage_chunk(S, 0, tid);   // prefetch chunk 0

    // residual <- emb + rr (frozen chain); rr0/rr1 = rr of rows gid / gid+8
    float rr0 = 0.f, rr1 = 0.f;
    for (int t2 = 0; t2 < 16; ++t2) {
        int m = wid * 16 + t2;
        const float* er = emb + (size_t)(n0 + m) * DIM;
        float* rw = resf + m * 129;
        float s = 0.f;
        #pragma unroll
        for (int q = 0; q < DIM / 32; ++q) {
            int d = lane + 32 * q;
            float v = er[d]; rw[d] = v; s = __fmaf_rn(v, v, s);
        }
        #pragma unroll
        for (int o = 16; o > 0; o >>= 1) s = __fadd_rn(s, __shfl_xor_sync(0xFFFFFFFFu, s, o));
        if (gid == t2)     rr0 = s;
        if (gid + 8 == t2) rr1 = s;
    }

    float lsum = 0.f;

    for (int c = 0; c < NCB; ++c) {
        const float* cbc = cb + (size_t)c * KCODES * DIM;

        __syncthreads();   // prev-cb readers done
        for (int e = tid; e < KCODES; e += TPB) wn_s[e] = g_wn[c * KCODES + e];

        // Build A fragments from residual (bf16), PTX m16n8k16 mapping:
        // a0:(row0, k=16kk+2c,+1) a1:(row1, same) a2:(row0, +8) a3:(row1, +8)
        uint32_t af[8][4];
        {
            const float* p0 = resf + row0 * 129;
            const float* p1 = resf + row1 * 129;
            #pragma unroll
            for (int kk = 0; kk < 8; ++kk) {
                int d = kk * 16 + 2 * cid;
                af[kk][0] = bf2(p0[d],     p0[d + 1]);
                af[kk][1] = bf2(p1[d],     p1[d + 1]);
                af[kk][2] = bf2(p0[d + 8], p0[d + 9]);
                af[kk][3] = bf2(p1[d + 8], p1[d + 9]);
            }
        }

        // per-row top-2 candidate lists (lane-local; lane scans 8 codes/chunk/row)
        float u0a = 1e30f, u0b = 1e30f, u1a = 1e30f, u1b = 1e30f;
        int   k0a = 0, k0b = 0, k1a = 0, k1b = 0;

        for (int t = 0; t < 32; ++t) {
            int g = c * 32 + t;
            __syncthreads();                       // all warps done with other buffer
            if (g + 1 < NCHUNK) { stage_chunk(S, g + 1, tid); CP_WAIT(1); }
            else                { CP_WAIT(0); }
            __syncthreads();                       // chunk g visible (+ wn first time)

            const __nv_bfloat16* Bs =
                reinterpret_cast<const __nv_bfloat16*>(S + SO_B + (g & 1) * BBUF);

            #pragma unroll
            for (int nt = 0; nt < 4; ++nt) {
                int code_n = nt * 8 + gid;         // this lane's B column
                const char* bp = reinterpret_cast<const char*>(Bs + code_n * 136 + 2 * cid);
                float cc[4] = {0.f, 0.f, 0.f, 0.f};
                #pragma unroll
                for (int kk = 0; kk < 8; ++kk) {
                    uint32_t b0 = *reinterpret_cast<const uint32_t*>(bp + kk * 32);
                    uint32_t b1 = *reinterpret_cast<const uint32_t*>(bp + kk * 32 + 16);
                    mma16816(cc, af[kk], b0, b1);
                }
                // C cols for this lane: 2c, 2c+1 of the n=8 tile
                int kb = t * 32 + nt * 8 + 2 * cid;
                float w0 = wn_s[kb], w1 = wn_s[kb + 1];
                float v;
                v = __fmaf_rn(-2.0f, cc[0], w0);   // row0, code kb
                if (v < u0b) { if (v < u0a) { u0b = u0a; k0b = k0a; u0a = v; k0a = kb; }
                               else        { u0b = v; k0b = kb; } }
                v = __fmaf_rn(-2.0f, cc[1], w1);   // row0, code kb+1
                if (v < u0b) { if (v < u0a) { u0b = u0a; k0b = k0a; u0a = v; k0a = kb + 1; }
                               else        { u0b = v; k0b = kb + 1; } }
                v = __fmaf_rn(-2.0f, cc[2], w0);   // row1, code kb
                if (v < u1b) { if (v < u1a) { u1b = u1a; k1b = k1a; u1a = v; k1a = kb; }
                               else        { u1b = v; k1b = kb; } }
                v = __fmaf_rn(-2.0f, cc[3], w1);   // row1, code kb+1
                if (v < u1b) { if (v < u1a) { u1b = u1a; k1b = k1a; u1a = v; k1a = kb + 1; }
                               else        { u1b = v; k1b = kb + 1; } }
            }
        }

        // exact rescore of this lane's 4 candidates (frozen chain)
        auto exact_u = [&](const float* rrow, float rr, int k) -> float {
            const float4* w4 = reinterpret_cast<const float4*>(cbc + (size_t)k * DIM);
            float lo = 0.f, hi = 0.f;
            #pragma unroll 8
            for (int q = 0; q < 32; ++q) {
                float4 w = __ldg(w4 + q);
                lo = __fmaf_rn(rrow[4 * q],     w.x, lo);
                hi = __fmaf_rn(rrow[4 * q + 1], w.y, hi);
                lo = __fmaf_rn(rrow[4 * q + 2], w.z, lo);
                hi = __fmaf_rn(rrow[4 * q + 3], w.w, hi);
            }
            float m_ = __fadd_rn(lo, hi);
            return __fadd_rn(__fmaf_rn(-2.0f, m_, rr), wn_s[k]);
        };
        const float* rp0 = resf + row0 * 129;
        const float* rp1 = resf + row1 * 129;

        float bU0, bU1; int bK0, bK1;
        {
            float ua = exact_u(rp0, rr0, k0a), ub = exact_u(rp0, rr0, k0b);
            bU0 = ua; bK0 = k0a;
            if (ub < bU0 || (ub == bU0 && k0b < bK0)) { bU0 = ub; bK0 = k0b; }
            ua = exact_u(rp1, rr1, k1a); ub = exact_u(rp1, rr1, k1b);
            bU1 = ua; bK1 = k1a;
            if (ub < bU1 || (ub == bU1 && k1b < bK1)) { bU1 = ub; bK1 = k1b; }
        }
        // quad merge (lanes cid 0..3 share rows): (u,k) min + threshold min
        float th0 = u0b, th1 = u1b;
        #pragma unroll
        for (int o = 1; o < 4; o <<= 1) {
            float ou; int ok;
            ou = __shfl_xor_sync(0xFFFFFFFFu, bU0, o);
            ok = __shfl_xor_sync(0xFFFFFFFFu, bK0, o);
            if (ou < bU0 || (ou == bU0 && ok < bK0)) { bU0 = ou; bK0 = ok; }
            ou = __shfl_xor_sync(0xFFFFFFFFu, bU1, o);
            ok = __shfl_xor_sync(0xFFFFFFFFu, bK1, o);
            if (ou < bU1 || (ou == bU1 && ok < bK1)) { bU1 = ou; bK1 = ok; }
            th0 = fminf(th0, __shfl_xor_sync(0xFFFFFFFFu, th0, o));
            th1 = fminf(th1, __shfl_xor_sync(0xFFFFFFFFu, th1, o));
        }
        float E0 = __fmaf_rn(0.017f, sqrtf(rr0 * g_wnmax[c]), 1e-4f);
        float E1 = __fmaf_rn(0.017f, sqrtf(rr1 * g_wnmax[c]), 1e-4f);
        bool need0 = !((rr0 + th0) - E0 > bU0 + 2e-5f);
        bool need1 = !((rr1 + th1) - E1 > bU1 + 2e-5f);
        // warp-uniform fallback: exact full scan, lane covers 256 codes per row
        if (__ballot_sync(0xFFFFFFFFu, need0 || need1)) {
            int kbeg = cid * 256, kend = kbeg + 256;
            float fU0 = 1e30f, fU1 = 1e30f; int fK0 = 0, fK1 = 0;
            for (int k = kbeg; k < kend; ++k) {
                float u = exact_u(rp0, rr0, k);
                if (u < fU0) { fU0 = u; fK0 = k; }
                u = exact_u(rp1, rr1, k);
                if (u < fU1) { fU1 = u; fK1 = k; }
            }
            #pragma unroll
            for (int o = 1; o < 4; o <<= 1) {
                float ou; int ok;
                ou = __shfl_xor_sync(0xFFFFFFFFu, fU0, o);
                ok = __shfl_xor_sync(0xFFFFFFFFu, fK0, o);
                if (ou < fU0 || (ou == fU0 && ok < fK0)) { fU0 = ou; fK0 = ok; }
                ou = __shfl_xor_sync(0xFFFFFFFFu, fU1, o);
                ok = __shfl_xor_sync(0xFFFFFFFFu, fK1, o);
                if (ou < fU1 || (ou == fU1 && ok < fK1)) { fU1 = ou; fK1 = ok; }
            }
            if (need0) { bU0 = fU0; bK0 = fK0; }
            if (need1) { bU1 = fU1; bK1 = fK1; }
        }
        if (cid == 0) {
            codes_s[c * M_TILE + row0] = bK0;
            codes_s[c * M_TILE + row1] = bK1;
            out_codes[(size_t)(n0 + row0) * NCB + c] = (float)bK0;
            out_codes[(size_t)(n0 + row1) * NCB + c] = (float)bK1;
        }

        __syncthreads();   // codes_s complete; rescore reads of resf done

        // residual update (exact elementwise chain) + loss
        for (int e = tid; e < M_TILE * DIM; e += TPB) {
            int m = e >> 7, d = e & 127;
            float w = cbc[(size_t)codes_s[c * M_TILE + m] * DIM + d];
            float rv = __fadd_rn(resf[m * 129 + d], -w);
            resf[m * 129 + d] = rv;
            lsum += rv * rv;
        }
        __syncthreads();   // updated residual visible

        // rr for next step (frozen warp-collective chain)
        for (int t2 = 0; t2 < 16; ++t2) {
            const float* rw = resf + (wid * 16 + t2) * 129;
            float s = 0.f;
            #pragma unroll
            for (int q = 0; q < DIM / 32; ++q) { float v = rw[lane + 32 * q]; s = __fmaf_rn(v, v, s); }
            #pragma unroll
            for (int o = 16; o > 0; o >>= 1) s = __fadd_rn(s, __shfl_xor_sync(0xFFFFFFFFu, s, o));
            if (gid == t2)     rr0 = s;
            if (gid + 8 == t2) rr1 = s;
        }
    }

    // quantized: q = sum_c w[idx_c] (reference add chain from 0); STE
    __syncthreads();
    for (int e = tid; e < M_TILE * DIM; e += TPB) {
        int m = e >> 7, d = e & 127;
        float q = cb[(size_t)codes_s[m] * DIM + d];
        #pragma unroll
        for (int c = 1; c < NCB; ++c)
            q = __fadd_rn(q, cb[(size_t)c * KCODES * DIM
                               + (size_t)codes_s[c * M_TILE + m] * DIM + d]);
        size_t g = (size_t)(n0 + m) * DIM + d;
        float e0 = emb[g];
        out_quant[g] = __fadd_rn(e0, __fadd_rn(q, -e0));
    }

    // deterministic block loss reduction
    red[tid] = lsum;
    __syncthreads();
    for (int s = TPB / 2; s > 0; s >>= 1) {
        if (tid < s) red[tid] += red[tid + s];
        __syncthreads();
    }
    if (tid == 0) g_part[blockIdx.x] = red[0];
}

// ---------------------------------------------------------------------------
__global__ void loss_final(float* __restrict__ out_loss) {
    __shared__ float red[GRID_MAIN];
    int t = threadIdx.x;
    red[t] = g_part[t];
    __syncthreads();
    for (int s = GRID_MAIN / 2; s > 0; s >>= 1) {
        if (t < s) red[t] += red[t + s];
        __syncthreads();
    }
    if (t == 0)
        out_loss[0] = red[0] * (1.0f / ((float)N_TOK * (float)DIM * (float)NCB));
}

// ---------------------------------------------------------------------------
extern "C" void kernel_launch(void* const* d_in, const int* in_sizes, int n_in,
                              void* d_out, int out_size) {
    const float* emb = (const float*)d_in[0];   // [8,4096,128] f32
    const float* cb  = (const float*)d_in[1];   // [8,1024,128] f32

    float* out_codes = (float*)d_out;                         // 32768*8
    float* out_quant = out_codes + (size_t)N_TOK * NCB;       // 32768*128
    float* out_loss  = out_quant + (size_t)N_TOK * DIM;       // 1

    cudaFuncSetAttribute(rvq_main, cudaFuncAttributeMaxDynamicSharedMemorySize, SMEM_REQ);

    wnorm_kernel<<<(NCB * KCODES) / 8, 256>>>(cb);
    wnmax_kernel<<<NCB, 256>>>();
    cb16_kernel<<<(NCB * KCODES * DIM + 255) / 256, 256>>>(cb);
    rvq_main<<<GRID_MAIN, TPB, SMEM_REQ>>>(emb, cb, out_codes, out_quant);
    loss_final<<<1, GRID_MAIN>>>(out_loss);
}

// round 15
// speedup vs baseline: 28.1858x; 28.1858x over previous
#include <cuda_runtime.h>
#include <cuda_bf16.h>
#include <cstddef>
#include <cstdint>

// Problem constants
#define N_TOK   32768
#define DIM     128
#define KCODES  1024
#define NCB     8
#define M_TILE  128
#define TPB     256
#define GRID_MAIN (N_TOK / M_TILE)    // 256
#define NCHUNK  256                   // 32-code chunks across all codebooks

// Device scratch (no allocations allowed)
__device__ float g_wn[NCB * KCODES];
__device__ float g_wnmax[NCB];
__device__ float g_part[GRID_MAIN];
__device__ __align__(16) __nv_bfloat16 g_cb16[(size_t)NCB * KCODES * DIM];

// smem offsets (16B aligned)
#define SO_RES   0         // float [128][129]   66048 B
#define SO_B     66048     // bf16 2 x [32][136] 17408 B
#define SO_WN    83456     // float [1024]        4096 B
#define SO_CODES 87552     // int [8][128]        4096 B
#define SO_RED   91648     // float [256]         1024 B
#define SMEM_REQ 92672
#define BBUF     8704      // one B buffer: 32*136*2

extern __shared__ char smraw[];

// ---------------------------------------------------------------------------
__device__ __forceinline__ uint32_t smem_u32(const void* p) {
    uint32_t a;
    asm("{ .reg .u64 t; cvta.to.shared.u64 t, %1; cvt.u32.u64 %0, t; }"
        : "=r"(a) : "l"(p));
    return a;
}
__device__ __forceinline__ void cp_async16(uint32_t dst, const void* src) {
    asm volatile("cp.async.cg.shared.global [%0], [%1], 16;\n" :: "r"(dst), "l"(src));
}
#define CP_COMMIT() asm volatile("cp.async.commit_group;\n" ::: "memory")
#define CP_WAIT(n)  asm volatile("cp.async.wait_group %0;\n" :: "n"(n) : "memory")

// pack two f32 into bf16x2: result.low = lo (even dim), result.high = hi (odd dim)
__device__ __forceinline__ uint32_t bf2(float lo, float hi) {
    uint32_t r;
    asm("cvt.rn.satfinite.bf16x2.f32 %0, %1, %2;" : "=r"(r) : "f"(hi), "f"(lo));
    return r;
}
// explicit HMMA: D(16x8,f32) += A(16x16,bf16,row) * B(16x8,bf16,col)
__device__ __forceinline__ void mma16816(float* c, const uint32_t* a,
                                         uint32_t b0, uint32_t b1) {
    asm volatile(
        "mma.sync.aligned.m16n8k16.row.col.f32.bf16.bf16.f32 "
        "{%0,%1,%2,%3}, {%4,%5,%6,%7}, {%8,%9}, {%0,%1,%2,%3};"
        : "+f"(c[0]), "+f"(c[1]), "+f"(c[2]), "+f"(c[3])
        : "r"(a[0]), "r"(a[1]), "r"(a[2]), "r"(a[3]), "r"(b0), "r"(b1));
}
// sorted top-4 insert (ascending), constant-indexed -> stays in registers
__device__ __forceinline__ void ins4(float v, int k, float* cu, int* ck) {
    if (v < cu[3]) {
        if (v < cu[1]) {
            if (v < cu[0]) {
                cu[3] = cu[2]; ck[3] = ck[2]; cu[2] = cu[1]; ck[2] = ck[1];
                cu[1] = cu[0]; ck[1] = ck[0]; cu[0] = v; ck[0] = k;
            } else {
                cu[3] = cu[2]; ck[3] = ck[2]; cu[2] = cu[1]; ck[2] = ck[1];
                cu[1] = v; ck[1] = k;
            }
        } else {
            if (v < cu[2]) { cu[3] = cu[2]; ck[3] = ck[2]; cu[2] = v; ck[2] = k; }
            else           { cu[3] = v; ck[3] = k; }
        }
    }
}

// ---------------------------------------------------------------------------
// Kernel 1: ||w||^2 per code (frozen chain)
// ---------------------------------------------------------------------------
__global__ void wnorm_kernel(const float* __restrict__ cb) {
    int gwarp = (blockIdx.x * blockDim.x + threadIdx.x) >> 5;
    int lane  = threadIdx.x & 31;
    if (gwarp >= NCB * KCODES) return;
    const float* w = cb + (size_t)gwarp * DIM;
    float s = 0.f;
    #pragma unroll
    for (int i = 0; i < DIM / 32; ++i) { float v = w[lane + 32 * i]; s = __fmaf_rn(v, v, s); }
    #pragma unroll
    for (int o = 16; o > 0; o >>= 1) s = __fadd_rn(s, __shfl_xor_sync(0xFFFFFFFFu, s, o));
    if (lane == 0) g_wn[gwarp] = s;
}

// Kernel 1b: per-codebook max ||w||^2
__global__ void wnmax_kernel() {
    __shared__ float red[256];
    int c = blockIdx.x, t = threadIdx.x;
    float mx = 0.f;
    for (int e = t; e < KCODES; e += 256) mx = fmaxf(mx, g_wn[c * KCODES + e]);
    red[t] = mx; __syncthreads();
    for (int s = 128; s > 0; s >>= 1) { if (t < s) red[t] = fmaxf(red[t], red[t + s]); __syncthreads(); }
    if (t == 0) g_wnmax[c] = red[0];
}

// Kernel 1c: codebook fp32 -> bf16 (row-major, same layout)
__global__ void cb16_kernel(const float* __restrict__ cb) {
    int i = blockIdx.x * blockDim.x + threadIdx.x;
    if (i < NCB * KCODES * DIM) g_cb16[i] = __float2bfloat16(cb[i]);
}

// ---------------------------------------------------------------------------
// stage one 32-code chunk: g_cb16 rows -> Bs[code][dim] bf16 (stride 136 elem)
// ---------------------------------------------------------------------------
__device__ __forceinline__ void stage_chunk(char* S, int g, int tid) {
    uint32_t dstb = smem_u32(S + SO_B + (g & 1) * BBUF);
    const char* src = (const char*)g_cb16 + (size_t)g * 32 * DIM * 2;   // 8192B
    #pragma unroll
    for (int r = 0; r < 2; ++r) {
        int e = tid + r * TPB;          // 0..511 x 16B
        int code = e >> 4, q = e & 15;
        cp_async16(dstb + code * 272 + q * 16, src + e * 16);
    }
    CP_COMMIT();
}

// ---------------------------------------------------------------------------
// Kernel 2: main. Block = 128 tokens, 8 warps; warp owns 16 tokens.
// mma.m16n8k16 prune -> per-lane top-4 (16 cand/token) -> windowed exact
// rescore (frozen chain) -> sound threshold -> rare per-token warp fallback.
// Codes bit-exact unconditionally.
// ---------------------------------------------------------------------------
__global__ __launch_bounds__(TPB, 2) void rvq_main(
    const float* __restrict__ emb, const float* __restrict__ cb,
    float* __restrict__ out_codes, float* __restrict__ out_quant)
{
    char* S = smraw;
    float* resf    = reinterpret_cast<float*>(S + SO_RES);
    float* wn_s    = reinterpret_cast<float*>(S + SO_WN);
    int*   codes_s = reinterpret_cast<int*>(S + SO_CODES);
    float* red     = reinterpret_cast<float*>(S + SO_RED);

    const int tid  = threadIdx.x;
    const int wid  = tid >> 5;
    const int lane = tid & 31;
    const int gid  = lane >> 2;        // group id 0..7 -> rows gid, gid+8
    const int cid  = lane & 3;
    const int n0   = blockIdx.x * M_TILE;
    const int row0 = wid * 16 + gid;
    const int row1 = row0 + 8;

    stage_chunk(S, 0, tid);   // prefetch chunk 0

    // residual <- emb + rr (frozen chain)
    float rr0 = 0.f, rr1 = 0.f;
    for (int t2 = 0; t2 < 16; ++t2) {
        int m = wid * 16 + t2;
        const float* er = emb + (size_t)(n0 + m) * DIM;
        float* rw = resf + m * 129;
        float s = 0.f;
        #pragma unroll
        for (int q = 0; q < DIM / 32; ++q) {
            int d = lane + 32 * q;
            float v = er[d]; rw[d] = v; s = __fmaf_rn(v, v, s);
        }
        #pragma unroll
        for (int o = 16; o > 0; o >>= 1) s = __fadd_rn(s, __shfl_xor_sync(0xFFFFFFFFu, s, o));
        if (gid == t2)     rr0 = s;
        if (gid + 8 == t2) rr1 = s;
    }

    float lsum = 0.f;

    for (int c = 0; c < NCB; ++c) {
        const float* cbc = cb + (size_t)c * KCODES * DIM;

        __syncthreads();   // prev-cb readers done
        for (int e = tid; e < KCODES; e += TPB) wn_s[e] = g_wn[c * KCODES + e];

        // A fragments (PTX m16n8k16 mapping)
        uint32_t af[8][4];
        {
            const float* p0 = resf + row0 * 129;
            const float* p1 = resf + row1 * 129;
            #pragma unroll
            for (int kk = 0; kk < 8; ++kk) {
                int d = kk * 16 + 2 * cid;
                af[kk][0] = bf2(p0[d],     p0[d + 1]);
                af[kk][1] = bf2(p1[d],     p1[d + 1]);
                af[kk][2] = bf2(p0[d + 8], p0[d + 9]);
                af[kk][3] = bf2(p1[d + 8], p1[d + 9]);
            }
        }

        // per-row per-lane top-4 (ascending)
        float cu0[4] = {1e30f, 1e30f, 1e30f, 1e30f};
        float cu1[4] = {1e30f, 1e30f, 1e30f, 1e30f};
        int   ck0[4] = {0, 0, 0, 0}, ck1[4] = {0, 0, 0, 0};

        for (int t = 0; t < 32; ++t) {
            int g = c * 32 + t;
            __syncthreads();
            if (g + 1 < NCHUNK) { stage_chunk(S, g + 1, tid); CP_WAIT(1); }
            else                { CP_WAIT(0); }
            __syncthreads();

            const __nv_bfloat16* Bs =
                reinterpret_cast<const __nv_bfloat16*>(S + SO_B + (g & 1) * BBUF);

            #pragma unroll
            for (int nt = 0; nt < 4; ++nt) {
                int code_n = nt * 8 + gid;
                const char* bp = reinterpret_cast<const char*>(Bs + code_n * 136 + 2 * cid);
                float cc[4] = {0.f, 0.f, 0.f, 0.f};
                #pragma unroll
                for (int kk = 0; kk < 8; ++kk) {
                    uint32_t b0 = *reinterpret_cast<const uint32_t*>(bp + kk * 32);
                    uint32_t b1 = *reinterpret_cast<const uint32_t*>(bp + kk * 32 + 16);
                    mma16816(cc, af[kk], b0, b1);
                }
                int kb = t * 32 + nt * 8 + 2 * cid;
                float w0 = wn_s[kb], w1 = wn_s[kb + 1];
                ins4(__fmaf_rn(-2.0f, cc[0], w0), kb,     cu0, ck0);
                ins4(__fmaf_rn(-2.0f, cc[1], w1), kb + 1, cu0, ck0);
                ins4(__fmaf_rn(-2.0f, cc[2], w0), kb,     cu1, ck1);
                ins4(__fmaf_rn(-2.0f, cc[3], w1), kb + 1, cu1, ck1);
            }
        }

        // quad stats: approx min (window center) and threshold (min of 4th-bests)
        float um0 = cu0[0], um1 = cu1[0], th0 = cu0[3], th1 = cu1[3];
        #pragma unroll
        for (int o = 1; o < 4; o <<= 1) {
            um0 = fminf(um0, __shfl_xor_sync(0xFFFFFFFFu, um0, o));
            um1 = fminf(um1, __shfl_xor_sync(0xFFFFFFFFu, um1, o));
            th0 = fminf(th0, __shfl_xor_sync(0xFFFFFFFFu, th0, o));
            th1 = fminf(th1, __shfl_xor_sync(0xFFFFFFFFu, th1, o));
        }
        // sound single-sided bf16 margin: E = 2*(2^-8+2^-18)*sqrt(rr*wnmax)+1e-4
        float wmx = g_wnmax[c];
        float E0 = __fmaf_rn(0.00785f, sqrtf(rr0 * wmx), 1e-4f);
        float E1 = __fmaf_rn(0.00785f, sqrtf(rr1 * wmx), 1e-4f);

        // windowed exact rescore (frozen chain)
        auto exact_u = [&](const float* rrow, float rr, int k) -> float {
            const float4* w4 = reinterpret_cast<const float4*>(cbc + (size_t)k * DIM);
            float lo = 0.f, hi = 0.f;
            #pragma unroll 8
            for (int q = 0; q < 32; ++q) {
                float4 w = __ldg(w4 + q);
                lo = __fmaf_rn(rrow[4 * q],     w.x, lo);
                hi = __fmaf_rn(rrow[4 * q + 1], w.y, hi);
                lo = __fmaf_rn(rrow[4 * q + 2], w.z, lo);
                hi = __fmaf_rn(rrow[4 * q + 3], w.w, hi);
            }
            float m_ = __fadd_rn(lo, hi);
            return __fadd_rn(__fmaf_rn(-2.0f, m_, rr), wn_s[k]);
        };
        const float* rp0 = resf + row0 * 129;
        const float* rp1 = resf + row1 * 129;
        float win0 = um0 + 2.0f * E0 + 4e-5f;
        float win1 = um1 + 2.0f * E1 + 4e-5f;
        float bU0 = 1e30f, bU1 = 1e30f; int bK0 = 0x7fffffff, bK1 = 0x7fffffff;
        #pragma unroll
        for (int s = 0; s < 4; ++s) {
            if (cu0[s] <= win0) {
                float u = exact_u(rp0, rr0, ck0[s]);
                if (u < bU0 || (u == bU0 && ck0[s] < bK0)) { bU0 = u; bK0 = ck0[s]; }
            }
            if (cu1[s] <= win1) {
                float u = exact_u(rp1, rr1, ck1[s]);
                if (u < bU1 || (u == bU1 && ck1[s] < bK1)) { bU1 = u; bK1 = ck1[s]; }
            }
        }
        #pragma unroll
        for (int o = 1; o < 4; o <<= 1) {
            float ou; int ok;
            ou = __shfl_xor_sync(0xFFFFFFFFu, bU0, o);
            ok = __shfl_xor_sync(0xFFFFFFFFu, bK0, o);
            if (ou < bU0 || (ou == bU0 && ok < bK0)) { bU0 = ou; bK0 = ok; }
            ou = __shfl_xor_sync(0xFFFFFFFFu, bU1, o);
            ok = __shfl_xor_sync(0xFFFFFFFFu, bK1, o);
            if (ou < bU1 || (ou == bU1 && ok < bK1)) { bU1 = ou; bK1 = ok; }
        }
        bool need0 = !((rr0 + th0) - E0 > bU0 + 2e-5f);
        bool need1 = !((rr1 + th1) - E1 > bU1 + 2e-5f);

        // rare fallback: per needy token, whole warp scans 1024 codes exactly
        unsigned mask0 = __ballot_sync(0xFFFFFFFFu, need0) & 0x11111111u;
        unsigned mask1 = __ballot_sync(0xFFFFFFFFu, need1) & 0x11111111u;
        while (mask0 | mask1) {
            int from0 = (mask0 != 0u);
            unsigned mm = from0 ? mask0 : mask1;
            int l = __ffs(mm) - 1;
            int gg = l >> 2;
            int m  = wid * 16 + gg + (from0 ? 0 : 8);
            if (from0) mask0 &= mask0 - 1u; else mask1 &= mask1 - 1u;

            const float* rp = resf + m * 129;
            float rrm = __shfl_sync(0xFFFFFFFFu, from0 ? rr0 : rr1, gg * 4);
            float fU = 1e30f; int fK = 0;
            for (int j = 0; j < 32; ++j) {
                int k = lane + 32 * j;          // wait no: keep per-lane ascending
                k = lane * 32 + j;              // lane covers 32 consecutive codes, ascending
                float u = exact_u(rp, rrm, k);
                if (u < fU) { fU = u; fK = k; } // ascending k: first-min kept
            }
            #pragma unroll
            for (int o = 1; o < 32; o <<= 1) {
                float ou = __shfl_xor_sync(0xFFFFFFFFu, fU, o);
                int   ok = __shfl_xor_sync(0xFFFFFFFFu, fK, o);
                if (ou < fU || (ou == fU && ok < fK)) { fU = ou; fK = ok; }
            }
            if (from0) { if (gid == gg && need0) { bU0 = fU; bK0 = fK; } }
            else       { if (gid == gg && need1) { bU1 = fU; bK1 = fK; } }
        }

        if (cid == 0) {
            codes_s[c * M_TILE + row0] = bK0;
            codes_s[c * M_TILE + row1] = bK1;
            out_codes[(size_t)(n0 + row0) * NCB + c] = (float)bK0;
            out_codes[(size_t)(n0 + row1) * NCB + c] = (float)bK1;
        }

        __syncthreads();   // codes_s complete; rescore reads of resf done

        // residual update (exact elementwise chain) + loss
        for (int e = tid; e < M_TILE * DIM; e += TPB) {
            int m = e >> 7, d = e & 127;
            float w = cbc[(size_t)codes_s[c * M_TILE + m] * DIM + d];
            float rv = __fadd_rn(resf[m * 129 + d], -w);
            resf[m * 129 + d] = rv;
            lsum += rv * rv;
        }
        __syncthreads();   // updated residual visible

        // rr for next step (frozen warp-collective chain)
        for (int t2 = 0; t2 < 16; ++t2) {
            const float* rw = resf + (wid * 16 + t2) * 129;
            float s = 0.f;
            #pragma unroll
            for (int q = 0; q < DIM / 32; ++q) { float v = rw[lane + 32 * q]; s = __fmaf_rn(v, v, s); }
            #pragma unroll
            for (int o = 16; o > 0; o >>= 1) s = __fadd_rn(s, __shfl_xor_sync(0xFFFFFFFFu, s, o));
            if (gid == t2)     rr0 = s;
            if (gid + 8 == t2) rr1 = s;
        }
    }

    // quantized: q = sum_c w[idx_c] (reference add chain from 0); STE
    __syncthreads();
    for (int e = tid; e < M_TILE * DIM; e += TPB) {
        int m = e >> 7, d = e & 127;
        float q = cb[(size_t)codes_s[m] * DIM + d];
        #pragma unroll
        for (int c = 1; c < NCB; ++c)
            q = __fadd_rn(q, cb[(size_t)c * KCODES * DIM
                               + (size_t)codes_s[c * M_TILE + m] * DIM + d]);
        size_t g = (size_t)(n0 + m) * DIM + d;
        float e0 = emb[g];
        out_quant[g] = __fadd_rn(e0, __fadd_rn(q, -e0));
    }

    // deterministic block loss reduction
    red[tid] = lsum;
    __syncthreads();
    for (int s = TPB / 2; s > 0; s >>= 1) {
        if (tid < s) red[tid] += red[tid + s];
        __syncthreads();
    }
    if (tid == 0) g_part[blockIdx.x] = red[0];
}

// ---------------------------------------------------------------------------
__global__ void loss_final(float* __restrict__ out_loss) {
    __shared__ float red[GRID_MAIN];
    int t = threadIdx.x;
    red[t] = g_part[t];
    __syncthreads();
    for (int s = GRID_MAIN / 2; s > 0; s >>= 1) {
        if (t < s) red[t] += red[t + s];
        __syncthreads();
    }
    if (t == 0)
        out_loss[0] = red[0] * (1.0f / ((float)N_TOK * (float)DIM * (float)NCB));
}

// ---------------------------------------------------------------------------
extern "C" void kernel_launch(void* const* d_in, const int* in_sizes, int n_in,
                              void* d_out, int out_size) {
    const float* emb = (const float*)d_in[0];   // [8,4096,128] f32
    const float* cb  = (const float*)d_in[1];   // [8,1024,128] f32

    float* out_codes = (float*)d_out;                         // 32768*8
    float* out_quant = out_codes + (size_t)N_TOK * NCB;       // 32768*128
    float* out_loss  = out_quant + (size_t)N_TOK * DIM;       // 1

    cudaFuncSetAttribute(rvq_main, cudaFuncAttributeMaxDynamicSharedMemorySize, SMEM_REQ);

    wnorm_kernel<<<(NCB * KCODES) / 8, 256>>>(cb);
    wnmax_kernel<<<NCB, 256>>>();
    cb16_kernel<<<(NCB * KCODES * DIM + 255) / 256, 256>>>(cb);
    rvq_main<<<GRID_MAIN, TPB, SMEM_REQ>>>(emb, cb, out_codes, out_quant);
    loss_final<<<1, GRID_MAIN>>>(out_loss);
}

// round 16
// speedup vs baseline: 28.6493x; 1.0164x over previous
#include <cuda_runtime.h>
#include <cuda_bf16.h>
#include <cstddef>
#include <cstdint>

// Problem constants
#define N_TOK   32768
#define DIM     128
#define KCODES  1024
#define NCB     8
#define M_TILE  128
#define TPB     256
#define GRID_MAIN (N_TOK / M_TILE)    // 256
#define NCHUNK  256                   // 32-code chunks across all codebooks

// Device scratch (no allocations allowed)
__device__ float g_wn[NCB * KCODES];
__device__ float g_wnmax[NCB];
__device__ float g_part[GRID_MAIN];
__device__ __align__(16) __nv_bfloat16 g_cb16[(size_t)NCB * KCODES * DIM];

// smem offsets (16B aligned)
#define SO_RES   0         // float [128][129]    66048 B
#define SO_B     66048     // bf16 4 x [32][136]  34816 B (ring of 4)
#define SO_WN    100864    // float [1024]         4096 B
#define SO_CODES 104960    // int [8][128]         4096 B
#define SO_RED   109056    // float [256]          1024 B
#define SMEM_REQ 110080
#define BBUF     8704      // one B buffer: 32*136*2

extern __shared__ char smraw[];

// ---------------------------------------------------------------------------
__device__ __forceinline__ uint32_t smem_u32(const void* p) {
    uint32_t a;
    asm("{ .reg .u64 t; cvta.to.shared.u64 t, %1; cvt.u32.u64 %0, t; }"
        : "=r"(a) : "l"(p));
    return a;
}
__device__ __forceinline__ void cp_async16(uint32_t dst, const void* src) {
    asm volatile("cp.async.cg.shared.global [%0], [%1], 16;\n" :: "r"(dst), "l"(src));
}
#define CP_COMMIT() asm volatile("cp.async.commit_group;\n" ::: "memory")
#define CP_WAIT(n)  asm volatile("cp.async.wait_group %0;\n" :: "n"(n) : "memory")

// pack two f32 into bf16x2: result.low = lo (even dim), result.high = hi (odd dim)
__device__ __forceinline__ uint32_t bf2(float lo, float hi) {
    uint32_t r;
    asm("cvt.rn.satfinite.bf16x2.f32 %0, %1, %2;" : "=r"(r) : "f"(hi), "f"(lo));
    return r;
}
// explicit HMMA: D(16x8,f32) += A(16x16,bf16,row) * B(16x8,bf16,col)
__device__ __forceinline__ void mma16816(float* c, const uint32_t* a,
                                         uint32_t b0, uint32_t b1) {
    asm volatile(
        "mma.sync.aligned.m16n8k16.row.col.f32.bf16.bf16.f32 "
        "{%0,%1,%2,%3}, {%4,%5,%6,%7}, {%8,%9}, {%0,%1,%2,%3};"
        : "+f"(c[0]), "+f"(c[1]), "+f"(c[2]), "+f"(c[3])
        : "r"(a[0]), "r"(a[1]), "r"(a[2]), "r"(a[3]), "r"(b0), "r"(b1));
}
// ldmatrix x4: 4 8x8 b16 matrices; lane 8m+r supplies row r of matrix m
__device__ __forceinline__ void ldm4(uint32_t* r, uint32_t addr) {
    asm volatile("ldmatrix.sync.aligned.m8n8.x4.shared.b16 {%0,%1,%2,%3}, [%4];"
                 : "=r"(r[0]), "=r"(r[1]), "=r"(r[2]), "=r"(r[3]) : "r"(addr));
}
// sorted top-4 insert (ascending), constant-indexed -> stays in registers
__device__ __forceinline__ void ins4(float v, int k, float* cu, int* ck) {
    if (v < cu[3]) {
        if (v < cu[1]) {
            if (v < cu[0]) {
                cu[3] = cu[2]; ck[3] = ck[2]; cu[2] = cu[1]; ck[2] = ck[1];
                cu[1] = cu[0]; ck[1] = ck[0]; cu[0] = v; ck[0] = k;
            } else {
                cu[3] = cu[2]; ck[3] = ck[2]; cu[2] = cu[1]; ck[2] = ck[1];
                cu[1] = v; ck[1] = k;
            }
        } else {
            if (v < cu[2]) { cu[3] = cu[2]; ck[3] = ck[2]; cu[2] = v; ck[2] = k; }
            else           { cu[3] = v; ck[3] = k; }
        }
    }
}

// ---------------------------------------------------------------------------
// Kernel 1: ||w||^2 per code (frozen chain)
// ---------------------------------------------------------------------------
__global__ void wnorm_kernel(const float* __restrict__ cb) {
    int gwarp = (blockIdx.x * blockDim.x + threadIdx.x) >> 5;
    int lane  = threadIdx.x & 31;
    if (gwarp >= NCB * KCODES) return;
    const float* w = cb + (size_t)gwarp * DIM;
    float s = 0.f;
    #pragma unroll
    for (int i = 0; i < DIM / 32; ++i) { float v = w[lane + 32 * i]; s = __fmaf_rn(v, v, s); }
    #pragma unroll
    for (int o = 16; o > 0; o >>= 1) s = __fadd_rn(s, __shfl_xor_sync(0xFFFFFFFFu, s, o));
    if (lane == 0) g_wn[gwarp] = s;
}

// Kernel 1b: per-codebook max ||w||^2
__global__ void wnmax_kernel() {
    __shared__ float red[256];
    int c = blockIdx.x, t = threadIdx.x;
    float mx = 0.f;
    for (int e = t; e < KCODES; e += 256) mx = fmaxf(mx, g_wn[c * KCODES + e]);
    red[t] = mx; __syncthreads();
    for (int s = 128; s > 0; s >>= 1) { if (t < s) red[t] = fmaxf(red[t], red[t + s]); __syncthreads(); }
    if (t == 0) g_wnmax[c] = red[0];
}

// Kernel 1c: codebook fp32 -> bf16 (row-major, same layout)
__global__ void cb16_kernel(const float* __restrict__ cb) {
    int i = blockIdx.x * blockDim.x + threadIdx.x;
    if (i < NCB * KCODES * DIM) g_cb16[i] = __float2bfloat16(cb[i]);
}

// ---------------------------------------------------------------------------
// stage one 32-code chunk: g_cb16 rows -> Bs[code][dim] bf16 (stride 136 elem)
// ---------------------------------------------------------------------------
__device__ __forceinline__ void stage_chunk(char* S, int g, int tid) {
    uint32_t dstb = smem_u32(S + SO_B + (g & 3) * BBUF);
    const char* src = (const char*)g_cb16 + (size_t)g * 32 * DIM * 2;   // 8192B
    #pragma unroll
    for (int r = 0; r < 2; ++r) {
        int e = tid + r * TPB;          // 0..511 x 16B
        int code = e >> 4, q = e & 15;
        cp_async16(dstb + code * 272 + q * 16, src + e * 16);
    }
    CP_COMMIT();
}

// ---------------------------------------------------------------------------
// Kernel 2: main. Block = 128 tokens, 8 warps; warp owns 16 tokens.
// mma.m16n8k16 prune (B via ldmatrix.x4) -> per-lane top-4 -> windowed exact
// rescore (frozen chain) -> sound threshold -> rare per-token warp fallback.
// Codes bit-exact unconditionally.
// ---------------------------------------------------------------------------
__global__ __launch_bounds__(TPB, 2) void rvq_main(
    const float* __restrict__ emb, const float* __restrict__ cb,
    float* __restrict__ out_codes, float* __restrict__ out_quant)
{
    char* S = smraw;
    float* resf    = reinterpret_cast<float*>(S + SO_RES);
    float* wn_s    = reinterpret_cast<float*>(S + SO_WN);
    int*   codes_s = reinterpret_cast<int*>(S + SO_CODES);
    float* red     = reinterpret_cast<float*>(S + SO_RED);

    const int tid  = threadIdx.x;
    const int wid  = tid >> 5;
    const int lane = tid & 31;
    const int gid  = lane >> 2;        // group id 0..7 -> rows gid, gid+8
    const int cid  = lane & 3;
    const int n0   = blockIdx.x * M_TILE;
    const int row0 = wid * 16 + gid;
    const int row1 = row0 + 8;
    // ldmatrix per-lane address part: row (lane&7) of matrix (lane>>3)
    const uint32_t lrow = (uint32_t)((lane & 7) * 272 + (lane >> 3) * 16);

    // prologue: stage chunks 0,1,2 (ring of 4, one group per chunk)
    stage_chunk(S, 0, tid);
    stage_chunk(S, 1, tid);
    stage_chunk(S, 2, tid);

    // residual <- emb + rr (frozen chain)
    float rr0 = 0.f, rr1 = 0.f;
    for (int t2 = 0; t2 < 16; ++t2) {
        int m = wid * 16 + t2;
        const float* er = emb + (size_t)(n0 + m) * DIM;
        float* rw = resf + m * 129;
        float s = 0.f;
        #pragma unroll
        for (int q = 0; q < DIM / 32; ++q) {
            int d = lane + 32 * q;
            float v = er[d]; rw[d] = v; s = __fmaf_rn(v, v, s);
        }
        #pragma unroll
        for (int o = 16; o > 0; o >>= 1) s = __fadd_rn(s, __shfl_xor_sync(0xFFFFFFFFu, s, o));
        if (gid == t2)     rr0 = s;
        if (gid + 8 == t2) rr1 = s;
    }

    float lsum = 0.f;

    for (int c = 0; c < NCB; ++c) {
        const float* cbc = cb + (size_t)c * KCODES * DIM;

        __syncthreads();   // prev-cb readers done (wn safe to overwrite)
        for (int e = tid; e < KCODES; e += TPB) wn_s[e] = g_wn[c * KCODES + e];

        // A fragments (PTX m16n8k16 mapping)
        uint32_t af[8][4];
        {
            const float* p0 = resf + row0 * 129;
            const float* p1 = resf + row1 * 129;
            #pragma unroll
            for (int kk = 0; kk < 8; ++kk) {
                int d = kk * 16 + 2 * cid;
                af[kk][0] = bf2(p0[d],     p0[d + 1]);
                af[kk][1] = bf2(p1[d],     p1[d + 1]);
                af[kk][2] = bf2(p0[d + 8], p0[d + 9]);
                af[kk][3] = bf2(p1[d + 8], p1[d + 9]);
            }
        }

        // per-row per-lane top-4 (ascending)
        float cu0[4] = {1e30f, 1e30f, 1e30f, 1e30f};
        float cu1[4] = {1e30f, 1e30f, 1e30f, 1e30f};
        int   ck0[4] = {0, 0, 0, 0}, ck1[4] = {0, 0, 0, 0};

        for (int t = 0; t < 32; ++t) {
            int g = c * 32 + t;
            CP_WAIT(2);        // stage(g) complete (groups g+1, g+2 may fly)
            __syncthreads();   // data visible + all warps done with buf (g-1)&3
            if (g + 3 < NCHUNK) stage_chunk(S, g + 3, tid);   // overwrites (g-1)&3
            else                CP_COMMIT();                  // keep group count

            const uint32_t bbase = smem_u32(S + SO_B + (g & 3) * BBUF) + lrow;

            #pragma unroll
            for (int nt = 0; nt < 4; ++nt) {
                // 4 x ldmatrix.x4: matrices = (codes nt*8..+7) x (k-octets 4j..4j+3)
                uint32_t b[4][4];
                #pragma unroll
                for (int j = 0; j < 4; ++j)
                    ldm4(b[j], bbase + (uint32_t)(nt * 2176 + j * 64));
                float cc[4] = {0.f, 0.f, 0.f, 0.f};
                #pragma unroll
                for (int j = 0; j < 4; ++j) {
                    mma16816(cc, af[2 * j],     b[j][0], b[j][1]);
                    mma16816(cc, af[2 * j + 1], b[j][2], b[j][3]);
                }
                int kb = t * 32 + nt * 8 + 2 * cid;
                float w0 = wn_s[kb], w1 = wn_s[kb + 1];
                ins4(__fmaf_rn(-2.0f, cc[0], w0), kb,     cu0, ck0);
                ins4(__fmaf_rn(-2.0f, cc[1], w1), kb + 1, cu0, ck0);
                ins4(__fmaf_rn(-2.0f, cc[2], w0), kb,     cu1, ck1);
                ins4(__fmaf_rn(-2.0f, cc[3], w1), kb + 1, cu1, ck1);
            }
        }

        // quad stats: approx min (window center) and threshold (min of 4th-bests)
        float um0 = cu0[0], um1 = cu1[0], th0 = cu0[3], th1 = cu1[3];
        #pragma unroll
        for (int o = 1; o < 4; o <<= 1) {
            um0 = fminf(um0, __shfl_xor_sync(0xFFFFFFFFu, um0, o));
            um1 = fminf(um1, __shfl_xor_sync(0xFFFFFFFFu, um1, o));
            th0 = fminf(th0, __shfl_xor_sync(0xFFFFFFFFu, th0, o));
            th1 = fminf(th1, __shfl_xor_sync(0xFFFFFFFFu, th1, o));
        }
        // sound single-sided bf16 margin
        float wmx = g_wnmax[c];
        float E0 = __fmaf_rn(0.00785f, sqrtf(rr0 * wmx), 1e-4f);
        float E1 = __fmaf_rn(0.00785f, sqrtf(rr1 * wmx), 1e-4f);

        // windowed exact rescore (frozen chain)
        auto exact_u = [&](const float* rrow, float rr, int k) -> float {
            const float4* w4 = reinterpret_cast<const float4*>(cbc + (size_t)k * DIM);
            float lo = 0.f, hi = 0.f;
            #pragma unroll 8
            for (int q = 0; q < 32; ++q) {
                float4 w = __ldg(w4 + q);
                lo = __fmaf_rn(rrow[4 * q],     w.x, lo);
                hi = __fmaf_rn(rrow[4 * q + 1], w.y, hi);
                lo = __fmaf_rn(rrow[4 * q + 2], w.z, lo);
                hi = __fmaf_rn(rrow[4 * q + 3], w.w, hi);
            }
            float m_ = __fadd_rn(lo, hi);
            return __fadd_rn(__fmaf_rn(-2.0f, m_, rr), wn_s[k]);
        };
        const float* rp0 = resf + row0 * 129;
        const float* rp1 = resf + row1 * 129;
        float win0 = um0 + 2.0f * E0 + 4e-5f;
        float win1 = um1 + 2.0f * E1 + 4e-5f;
        float bU0 = 1e30f, bU1 = 1e30f; int bK0 = 0x7fffffff, bK1 = 0x7fffffff;
        #pragma unroll
        for (int s = 0; s < 4; ++s) {
            if (cu0[s] <= win0) {
                float u = exact_u(rp0, rr0, ck0[s]);
                if (u < bU0 || (u == bU0 && ck0[s] < bK0)) { bU0 = u; bK0 = ck0[s]; }
            }
            if (cu1[s] <= win1) {
                float u = exact_u(rp1, rr1, ck1[s]);
                if (u < bU1 || (u == bU1 && ck1[s] < bK1)) { bU1 = u; bK1 = ck1[s]; }
            }
        }
        #pragma unroll
        for (int o = 1; o < 4; o <<= 1) {
            float ou; int ok;
            ou = __shfl_xor_sync(0xFFFFFFFFu, bU0, o);
            ok = __shfl_xor_sync(0xFFFFFFFFu, bK0, o);
            if (ou < bU0 || (ou == bU0 && ok < bK0)) { bU0 = ou; bK0 = ok; }
            ou = __shfl_xor_sync(0xFFFFFFFFu, bU1, o);
            ok = __shfl_xor_sync(0xFFFFFFFFu, bK1, o);
            if (ou < bU1 || (ou == bU1 && ok < bK1)) { bU1 = ou; bK1 = ok; }
        }
        bool need0 = !((rr0 + th0) - E0 > bU0 + 2e-5f);
        bool need1 = !((rr1 + th1) - E1 > bU1 + 2e-5f);

        // rare fallback: per needy token, whole warp scans 1024 codes exactly
        unsigned mask0 = __ballot_sync(0xFFFFFFFFu, need0) & 0x11111111u;
        unsigned mask1 = __ballot_sync(0xFFFFFFFFu, need1) & 0x11111111u;
        while (mask0 | mask1) {
            int from0 = (mask0 != 0u);
            unsigned mm = from0 ? mask0 : mask1;
            int l = __ffs(mm) - 1;
            int gg = l >> 2;
            int m  = wid * 16 + gg + (from0 ? 0 : 8);
            if (from0) mask0 &= mask0 - 1u; else mask1 &= mask1 - 1u;

            const float* rp = resf + m * 129;
            float rrm = __shfl_sync(0xFFFFFFFFu, from0 ? rr0 : rr1, gg * 4);
            float fU = 1e30f; int fK = 0;
            for (int j = 0; j < 32; ++j) {
                int k = lane * 32 + j;          // lane covers 32 consecutive codes, ascending
                float u = exact_u(rp, rrm, k);
                if (u < fU) { fU = u; fK = k; } // ascending k: first-min kept
            }
            #pragma unroll
            for (int o = 1; o < 32; o <<= 1) {
                float ou = __shfl_xor_sync(0xFFFFFFFFu, fU, o);
                int   ok = __shfl_xor_sync(0xFFFFFFFFu, fK, o);
                if (ou < fU || (ou == fU && ok < fK)) { fU = ou; fK = ok; }
            }
            if (from0) { if (gid == gg && need0) { bU0 = fU; bK0 = fK; } }
            else       { if (gid == gg && need1) { bU1 = fU; bK1 = fK; } }
        }

        if (cid == 0) {
            codes_s[c * M_TILE + row0] = bK0;
            codes_s[c * M_TILE + row1] = bK1;
            out_codes[(size_t)(n0 + row0) * NCB + c] = (float)bK0;
            out_codes[(size_t)(n0 + row1) * NCB + c] = (float)bK1;
        }

        __syncthreads();   // codes_s complete; rescore reads of resf done

        // residual update (exact elementwise chain) + loss
        for (int e = tid; e < M_TILE * DIM; e += TPB) {
            int m = e >> 7, d = e & 127;
            float w = cbc[(size_t)codes_s[c * M_TILE + m] * DIM + d];
            float rv = __fadd_rn(resf[m * 129 + d], -w);
            resf[m * 129 + d] = rv;
            lsum += rv * rv;
        }
        __syncthreads();   // updated residual visible

        // rr for next step (frozen warp-collective chain)
        for (int t2 = 0; t2 < 16; ++t2) {
            const float* rw = resf + (wid * 16 + t2) * 129;
            float s = 0.f;
            #pragma unroll
            for (int q = 0; q < DIM / 32; ++q) { float v = rw[lane + 32 * q]; s = __fmaf_rn(v, v, s); }
            #pragma unroll
            for (int o = 16; o > 0; o >>= 1) s = __fadd_rn(s, __shfl_xor_sync(0xFFFFFFFFu, s, o));
            if (gid == t2)     rr0 = s;
            if (gid + 8 == t2) rr1 = s;
        }
    }

    // quantized: q = sum_c w[idx_c] (reference add chain from 0); STE
    __syncthreads();
    for (int e = tid; e < M_TILE * DIM; e += TPB) {
        int m = e >> 7, d = e & 127;
        float q = cb[(size_t)codes_s[m] * DIM + d];
        #pragma unroll
        for (int c = 1; c < NCB; ++c)
            q = __fadd_rn(q, cb[(size_t)c * KCODES * DIM
                               + (size_t)codes_s[c * M_TILE + m] * DIM + d]);
        size_t g = (size_t)(n0 + m) * DIM + d;
        float e0 = emb[g];
        out_quant[g] = __fadd_rn(e0, __fadd_rn(q, -e0));
    }

    // deterministic block loss reduction
    red[tid] = lsum;
    __syncthreads();
    for (int s = TPB / 2; s > 0; s >>= 1) {
        if (tid < s) red[tid] += red[tid + s];
        __syncthreads();
    }
    if (tid == 0) g_part[blockIdx.x] = red[0];
}

// ---------------------------------------------------------------------------
__global__ void loss_final(float* __restrict__ out_loss) {
    __shared__ float red[GRID_MAIN];
    int t = threadIdx.x;
    red[t] = g_part[t];
    __syncthreads();
    for (int s = GRID_MAIN / 2; s > 0; s >>= 1) {
        if (t < s) red[t] += red[t + s];
        __syncthreads();
    }
    if (t == 0)
        out_loss[0] = red[0] * (1.0f / ((float)N_TOK * (float)DIM * (float)NCB));
}

// ---------------------------------------------------------------------------
extern "C" void kernel_launch(void* const* d_in, const int* in_sizes, int n_in,
                              void* d_out, int out_size) {
    const float* emb = (const float*)d_in[0];   // [8,4096,128] f32
    const float* cb  = (const float*)d_in[1];   // [8,1024,128] f32

    float* out_codes = (float*)d_out;                         // 32768*8
    float* out_quant = out_codes + (size_t)N_TOK * NCB;       // 32768*128
    float* out_loss  = out_quant + (size_t)N_TOK * DIM;       // 1

    cudaFuncSetAttribute(rvq_main, cudaFuncAttributeMaxDynamicSharedMemorySize, SMEM_REQ);

    wnorm_kernel<<<(NCB * KCODES) / 8, 256>>>(cb);
    wnmax_kernel<<<NCB, 256>>>();
    cb16_kernel<<<(NCB * KCODES * DIM + 255) / 256, 256>>>(cb);
    rvq_main<<<GRID_MAIN, TPB, SMEM_REQ>>>(emb, cb, out_codes, out_quant);
    loss_final<<<1, GRID_MAIN>>>(out_loss);
}